// round 10
// baseline (speedup 1.0000x reference)
#include <cuda_runtime.h>
#include <stdint.h>

#define BATCH 64
#define TT    512
#define HH    768
#define KK    4
#define ROWS  (BATCH*TT)   // 32768
#define NCHUNK 32
#define CL     16          // backtrack chunk length (NCHUNK*CL = 512)

// Scratch (no cudaMalloc allowed). All [t][b]-major for coalesced lane access.
__device__ float4   g_emis[(TT+8)*BATCH];   // [t*64+b], +8 rows padding for prefetch overrun
__device__ float4   g_scores[TT*BATCH];     // [t*64+b] viterbi scores
__device__ unsigned g_map32[TT*BATCH];      // [s*64+b] byte-form backpointer map (s=0..510)
__device__ unsigned g_cmap[NCHUNK*BATCH];   // [c*64+b] chunk-composed map
__device__ int      g_best[BATCH];

// pack byte-form map (bytes 0..3, values 0..3) into a PRMT nibble selector
__device__ __forceinline__ unsigned nibsel(unsigned x) {
    unsigned y = x | (x >> 4);
    unsigned t = y & 0x00FF00FFu;
    return (t | (t >> 8)) & 0xFFFFu;
}

// ---------------------------------------------------------------------------
// K1: emissions[b,t,k] = sum_h sentences[b,t,h]*W[k,h] + bias[k]
// warp-per-row, W in shared, float4 coalesced, shuffle reduce. HBM-bound.
// Stores TRANSPOSED: g_emis[t*64 + b].
// ---------------------------------------------------------------------------
__global__ __launch_bounds__(256) void k_emissions(
    const float* __restrict__ sent,   // [B,T,H]
    const float* __restrict__ W,      // [K,H]
    const float* __restrict__ bias)   // [K]
{
    __shared__ float4 sW[KK][HH/4];   // 12 KB
    __shared__ float  sb[KK];
    int tid = threadIdx.x;

    const float4* W4 = (const float4*)W;
    for (int i = tid; i < KK*(HH/4); i += blockDim.x)
        sW[i/(HH/4)][i%(HH/4)] = W4[i];
    if (tid < KK) sb[tid] = bias[tid];
    __syncthreads();

    int warp = tid >> 5, lane = tid & 31;
    int row  = blockIdx.x * (blockDim.x >> 5) + warp;
    if (row >= ROWS) return;

    const float4* x = (const float4*)(sent + (size_t)row * HH);
    float a0 = 0.f, a1 = 0.f, a2 = 0.f, a3 = 0.f;
    #pragma unroll
    for (int i = 0; i < HH/128; i++) {            // 6 iterations
        int idx = i*32 + lane;
        float4 v  = x[idx];
        float4 w0 = sW[0][idx];
        float4 w1 = sW[1][idx];
        float4 w2 = sW[2][idx];
        float4 w3 = sW[3][idx];
        a0 += v.x*w0.x + v.y*w0.y + v.z*w0.z + v.w*w0.w;
        a1 += v.x*w1.x + v.y*w1.y + v.z*w1.z + v.w*w1.w;
        a2 += v.x*w2.x + v.y*w2.y + v.z*w2.z + v.w*w2.w;
        a3 += v.x*w3.x + v.y*w3.y + v.z*w3.z + v.w*w3.w;
    }
    #pragma unroll
    for (int d = 16; d; d >>= 1) {
        a0 += __shfl_xor_sync(0xffffffffu, a0, d);
        a1 += __shfl_xor_sync(0xffffffffu, a1, d);
        a2 += __shfl_xor_sync(0xffffffffu, a2, d);
        a3 += __shfl_xor_sync(0xffffffffu, a3, d);
    }
    if (lane == 0) {
        int b = row >> 9;            // row / TT
        int t = row & (TT-1);        // row % TT
        g_emis[t*BATCH + b] = make_float4(a0 + sb[0], a1 + sb[1], a2 + sb[2], a3 + sb[3]);
    }
}

// ---------------------------------------------------------------------------
// K2: Viterbi forward scan, 2 threads per batch (h in {0,1} handles tags
// j = 2h, 2h+1). Partner scores via single-level shfl_xor (same warp).
// EXACT: each FADD identical to reference; fp max is exactly associative,
// so the split max tree is bitwise-identical.
// ---------------------------------------------------------------------------
__global__ __launch_bounds__(128) void k_forward(
    const float* __restrict__ startT,
    const float* __restrict__ endT,
    const float* __restrict__ trans)   // [K,K], trans[i*4+j]
{
    int tid = threadIdx.x;
    int b = tid >> 1, h = tid & 1;
    int j0 = 2*h, j1 = 2*h + 1;        // my target tags
    int i0 = 2*h, i1 = 2*h + 1;        // my resident score indices
    int o0 = 2 - 2*h, o1 = 3 - 2*h;    // partner's score indices

    float Ta0 = __ldg(trans + i0*4 + j0), Tb0 = __ldg(trans + i1*4 + j0);
    float Tc0 = __ldg(trans + o0*4 + j0), Td0 = __ldg(trans + o1*4 + j0);
    float Ta1 = __ldg(trans + i0*4 + j1), Tb1 = __ldg(trans + i1*4 + j1);
    float Tc1 = __ldg(trans + o0*4 + j1), Td1 = __ldg(trans + o1*4 + j1);

    const float2* em = (const float2*)g_emis;   // [(t*64+b)*2 + h]
    float2*       sc = (float2*)g_scores;

    float2 e0 = em[(0*BATCH + b)*2 + h];
    float p0 = __ldg(startT + j0) + e0.x;
    float p1 = __ldg(startT + j1) + e0.y;
    sc[(0*BATCH + b)*2 + h] = make_float2(p0, p1);

    float2 buf[8];
    #pragma unroll
    for (int j = 0; j < 8; j++) buf[j] = em[((1 + j)*BATCH + b)*2 + h];

    // main: t = 1..504, unconditional prefetch (array padded to TT+8 rows)
    for (int base = 1; base <= 497; base += 8) {
        #pragma unroll
        for (int j = 0; j < 8; j++) {
            int t = base + j;
            float2 e = buf[j];
            buf[j] = em[((t + 8)*BATCH + b)*2 + h];

            float q0 = __shfl_xor_sync(0xffffffffu, p0, 1);
            float q1 = __shfl_xor_sync(0xffffffffu, p1, 1);
            float own0 = fmaxf(p0 + Ta0, p1 + Tb0);
            float own1 = fmaxf(p0 + Ta1, p1 + Tb1);
            float oth0 = fmaxf(q0 + Tc0, q1 + Td0);
            float oth1 = fmaxf(q0 + Tc1, q1 + Td1);
            float n0 = fmaxf(own0, oth0) + e.x;
            float n1 = fmaxf(own1, oth1) + e.y;
            p0 = n0; p1 = n1;
            sc[(t*BATCH + b)*2 + h] = make_float2(p0, p1);
        }
    }

    // tail: t = 505..511 (buf[j] holds em[505+j] after last group)
    #pragma unroll
    for (int j = 0; j < 7; j++) {
        int t = 505 + j;
        float2 e = buf[j];
        float q0 = __shfl_xor_sync(0xffffffffu, p0, 1);
        float q1 = __shfl_xor_sync(0xffffffffu, p1, 1);
        float own0 = fmaxf(p0 + Ta0, p1 + Tb0);
        float own1 = fmaxf(p0 + Ta1, p1 + Tb1);
        float oth0 = fmaxf(q0 + Tc0, q1 + Td0);
        float oth1 = fmaxf(q0 + Tc1, q1 + Td1);
        float n0 = fmaxf(own0, oth0) + e.x;
        float n1 = fmaxf(own1, oth1) + e.y;
        p0 = n0; p1 = n1;
        sc[(t*BATCH + b)*2 + h] = make_float2(p0, p1);
    }

    // final: add end transitions, argmax over 4 (strict >, first index wins)
    float f0 = p0 + __ldg(endT + j0);
    float f1 = p1 + __ldg(endT + j1);
    float g0 = __shfl_xor_sync(0xffffffffu, f0, 1);
    float g1 = __shfl_xor_sync(0xffffffffu, f1, 1);
    if (h == 0) {
        // order: f0=s0+e0, f1=s1+e1, g0=s2+e2, g1=s3+e3
        int best = 0; float m = f0;
        if (f1 > m) { m = f1; best = 1; }
        if (g0 > m) { m = g0; best = 2; }
        if (g1 > m) { m = g1; best = 3; }
        g_best[b] = best;
    }
}

// ---------------------------------------------------------------------------
// K3: per (chunk c, batch b): per-step backpointer maps
//   f_s[j] = argmax_i ( scores[s][i] + trans[i][j] ), first-index wins,
// stored + chunk-composed map F_c (exact integer composition via PRMT).
// ---------------------------------------------------------------------------
__global__ __launch_bounds__(64) void k_chunk(const float* __restrict__ trans)
{
    int b = threadIdx.x;
    int c = blockIdx.x;
    int sbase = c * CL;
    int ns = (c == NCHUNK-1) ? (CL-1) : CL;   // chunk 31 covers s=496..510

    float tr[16];
    #pragma unroll
    for (int i = 0; i < 16; i++) tr[i] = __ldg(trans + i);

    unsigned m[CL];
    #pragma unroll
    for (int k = 0; k < CL; k++) {
        if (k < ns) {
            float4 sc = g_scores[(sbase + k)*BATCH + b];
            unsigned hh = 0;
            #pragma unroll
            for (int j = 0; j < 4; j++) {
                float c0 = sc.x + tr[0*4+j];
                float c1 = sc.y + tr[1*4+j];
                float c2 = sc.z + tr[2*4+j];
                float c3 = sc.w + tr[3*4+j];
                int bp = 0; float mm = c0;
                if (c1 > mm) { mm = c1; bp = 1; }
                if (c2 > mm) { mm = c2; bp = 2; }
                if (c3 > mm) { mm = c3; bp = 3; }
                hh |= (unsigned)bp << (8*j);
            }
            m[k] = hh;
            g_map32[(sbase + k)*BATCH + b] = hh;
        }
    }

    unsigned F = m[ns-1];
    #pragma unroll
    for (int k = CL-2; k >= 0; k--)
        if (k <= ns-2)
            F = __byte_perm(m[k], 0, nibsel(F));
    g_cmap[c*BATCH + b] = F;
}

// ---------------------------------------------------------------------------
// K4: chunk replay with inline suffix walk (k_btag fused away).
// Each block derives its incoming tag from g_best via the chunk-map suffix,
// then replays its 16 steps. Block NCHUNK-1 writes out[511].
// ---------------------------------------------------------------------------
__global__ __launch_bounds__(64) void k_replay(float* __restrict__ out)
{
    int b = threadIdx.x;
    int c = blockIdx.x;
    int sbase = c * CL;
    int ns = (c == NCHUNK-1) ? (CL-1) : CL;

    int tag = g_best[b];
    if (c == NCHUNK-1) out[b*TT + (TT-1)] = (float)tag;
    for (int cc = NCHUNK-1; cc > c; cc--)
        tag = __byte_perm(g_cmap[cc*BATCH + b], 0, tag) & 3;

    unsigned m[CL];
    #pragma unroll
    for (int k = 0; k < CL; k++)
        if (k < ns) m[k] = g_map32[(sbase + k)*BATCH + b];

    #pragma unroll
    for (int k = CL-1; k >= 0; k--) {
        if (k < ns) {
            tag = __byte_perm(m[k], 0, tag) & 3;
            out[b*TT + sbase + k] = (float)tag;
        }
    }
}

// ---------------------------------------------------------------------------
// Bind inputs BY ELEMENT COUNT (robust to input-order permutation).
// The three 4-element vectors keep their relative order: b, start, end.
// __output__ dtype is float32 (established R7).
// ---------------------------------------------------------------------------
extern "C" void kernel_launch(void* const* d_in, const int* in_sizes, int n_in,
                              void* d_out, int out_size)
{
    const float* sent   = 0;
    const float* W      = 0;
    const float* bias   = 0;
    const float* startT = 0;
    const float* endT   = 0;
    const float* trans  = 0;

    int n4 = 0;
    for (int i = 0; i < n_in; i++) {
        int sz = in_sizes[i];
        const float* p = (const float*)d_in[i];
        if      (sz == BATCH*TT*HH) sent  = p;
        else if (sz == KK*HH)       W     = p;
        else if (sz == KK*KK)       trans = p;
        else if (sz == KK) {
            if      (n4 == 0) bias   = p;
            else if (n4 == 1) startT = p;
            else              endT   = p;
            n4++;
        }
    }
    float* out = (float*)d_out;                   // [64,512] float32

    k_emissions<<<ROWS/8, 256>>>(sent, W, bias);
    k_forward<<<1, 128>>>(startT, endT, trans);
    k_chunk<<<NCHUNK, 64>>>(trans);
    k_replay<<<NCHUNK, 64>>>(out);
}

// round 14
// speedup vs baseline: 1.2566x; 1.2566x over previous
#include <cuda_runtime.h>
#include <stdint.h>

#define BATCH 64
#define TT    512
#define HH    768
#define KK    4
#define ROWS  (BATCH*TT)   // 32768
#define NCHUNK 32
#define CL     16          // chunk length (NCHUNK*CL = 512)

// Scratch (no cudaMalloc allowed). [t][b]-major for coalesced lane access.
__device__ float4   g_emis[(TT+8)*BATCH];   // [t*64+b], +8 rows pad for prefetch overrun
__device__ float4   g_scores[TT*BATCH];     // [t*64+b] viterbi scores
__device__ unsigned g_map32[TT*BATCH];      // [s*64+b] byte-form backpointer maps

// pack byte-form map (bytes 0..3, values 0..3) into a PRMT nibble selector
__device__ __forceinline__ unsigned nibsel(unsigned x) {
    unsigned y = x | (x >> 4);
    unsigned t = y & 0x00FF00FFu;
    return (t | (t >> 8)) & 0xFFFFu;
}

// ---------------------------------------------------------------------------
// K1: emissions[b,t,k] = sum_h sentences[b,t,h]*W[k,h] + bias[k]
// warp-per-row, W in shared, float4 coalesced, shuffle reduce. HBM-bound.
// Stores TRANSPOSED: g_emis[t*64 + b].  (unchanged from R8)
// ---------------------------------------------------------------------------
__global__ __launch_bounds__(256) void k_emissions(
    const float* __restrict__ sent,   // [B,T,H]
    const float* __restrict__ W,      // [K,H]
    const float* __restrict__ bias)   // [K]
{
    __shared__ float4 sW[KK][HH/4];   // 12 KB
    __shared__ float  sb[KK];
    int tid = threadIdx.x;

    const float4* W4 = (const float4*)W;
    for (int i = tid; i < KK*(HH/4); i += blockDim.x)
        sW[i/(HH/4)][i%(HH/4)] = W4[i];
    if (tid < KK) sb[tid] = bias[tid];
    __syncthreads();

    int warp = tid >> 5, lane = tid & 31;
    int row  = blockIdx.x * (blockDim.x >> 5) + warp;
    if (row >= ROWS) return;

    const float4* x = (const float4*)(sent + (size_t)row * HH);
    float a0 = 0.f, a1 = 0.f, a2 = 0.f, a3 = 0.f;
    #pragma unroll
    for (int i = 0; i < HH/128; i++) {            // 6 iterations
        int idx = i*32 + lane;
        float4 v  = x[idx];
        float4 w0 = sW[0][idx];
        float4 w1 = sW[1][idx];
        float4 w2 = sW[2][idx];
        float4 w3 = sW[3][idx];
        a0 += v.x*w0.x + v.y*w0.y + v.z*w0.z + v.w*w0.w;
        a1 += v.x*w1.x + v.y*w1.y + v.z*w1.z + v.w*w1.w;
        a2 += v.x*w2.x + v.y*w2.y + v.z*w2.z + v.w*w2.w;
        a3 += v.x*w3.x + v.y*w3.y + v.z*w3.z + v.w*w3.w;
    }
    #pragma unroll
    for (int d = 16; d; d >>= 1) {
        a0 += __shfl_xor_sync(0xffffffffu, a0, d);
        a1 += __shfl_xor_sync(0xffffffffu, a1, d);
        a2 += __shfl_xor_sync(0xffffffffu, a2, d);
        a3 += __shfl_xor_sync(0xffffffffu, a3, d);
    }
    if (lane == 0) {
        int b = row >> 9;
        int t = row & (TT-1);
        g_emis[t*BATCH + b] = make_float4(a0 + sb[0], a1 + sb[1], a2 + sb[2], a3 + sb[3]);
    }
}

// ---------------------------------------------------------------------------
// K2 (FUSED): forward scan + chunk maps + suffix walk + replay + write-out.
// One block, 512 threads, phases separated by __syncthreads (which orders
// both shared and global accesses within the block; grid has one block).
// Static smem total ~42.3 KB < 48 KB static limit.
// Phase A is the R8 64-thread forward loop verbatim (known-good perf, exact).
// ---------------------------------------------------------------------------
__global__ __launch_bounds__(512) void k_viterbi(
    const float* __restrict__ startT,
    const float* __restrict__ endT,
    const float* __restrict__ trans,   // [K,K], trans[i*4+j]
    float* __restrict__ out)           // [B,T] float32
{
    __shared__ unsigned s_cmap[NCHUNK*BATCH];   // 8 KB  composed chunk maps
    __shared__ uint8_t  s_btag[NCHUNK*BATCH];   // 2 KB  incoming tag per chunk
    __shared__ uint4    s_tag[NCHUNK*BATCH];    // 32 KB tags, [c*64+b] 16 bytes
    __shared__ int      s_best[BATCH];

    int tid = threadIdx.x;

    // ---------------- Phase A: forward scan (threads 0..63, as R8) ----------
    if (tid < 64) {
        int b = tid;
        float T00=__ldg(trans+ 0), T01=__ldg(trans+ 1), T02=__ldg(trans+ 2), T03=__ldg(trans+ 3);
        float T10=__ldg(trans+ 4), T11=__ldg(trans+ 5), T12=__ldg(trans+ 6), T13=__ldg(trans+ 7);
        float T20=__ldg(trans+ 8), T21=__ldg(trans+ 9), T22=__ldg(trans+10), T23=__ldg(trans+11);
        float T30=__ldg(trans+12), T31=__ldg(trans+13), T32=__ldg(trans+14), T33=__ldg(trans+15);

        float4 e0 = g_emis[0*BATCH + b];
        float s0 = __ldg(startT+0) + e0.x;
        float s1 = __ldg(startT+1) + e0.y;
        float s2 = __ldg(startT+2) + e0.z;
        float s3 = __ldg(startT+3) + e0.w;
        g_scores[0*BATCH + b] = make_float4(s0, s1, s2, s3);

        float4 buf[8];
        #pragma unroll
        for (int j = 0; j < 8; j++) buf[j] = g_emis[(1 + j)*BATCH + b];

        for (int base = 1; base <= 497; base += 8) {
            #pragma unroll
            for (int j = 0; j < 8; j++) {
                int t = base + j;
                float4 e = buf[j];
                buf[j] = g_emis[(t + 8)*BATCH + b];   // safe: padded rows

                float c0, c1, c2, c3, n0, n1, n2, n3;
                c0 = s0 + T00; c1 = s1 + T10; c2 = s2 + T20; c3 = s3 + T30;
                n0 = fmaxf(fmaxf(c0, c1), fmaxf(c2, c3)) + e.x;
                c0 = s0 + T01; c1 = s1 + T11; c2 = s2 + T21; c3 = s3 + T31;
                n1 = fmaxf(fmaxf(c0, c1), fmaxf(c2, c3)) + e.y;
                c0 = s0 + T02; c1 = s1 + T12; c2 = s2 + T22; c3 = s3 + T32;
                n2 = fmaxf(fmaxf(c0, c1), fmaxf(c2, c3)) + e.z;
                c0 = s0 + T03; c1 = s1 + T13; c2 = s2 + T23; c3 = s3 + T33;
                n3 = fmaxf(fmaxf(c0, c1), fmaxf(c2, c3)) + e.w;
                s0 = n0; s1 = n1; s2 = n2; s3 = n3;
                g_scores[t*BATCH + b] = make_float4(s0, s1, s2, s3);
            }
        }
        #pragma unroll
        for (int j = 0; j < 7; j++) {
            int t = 505 + j;
            float4 e = buf[j];
            float c0, c1, c2, c3, n0, n1, n2, n3;
            c0 = s0 + T00; c1 = s1 + T10; c2 = s2 + T20; c3 = s3 + T30;
            n0 = fmaxf(fmaxf(c0, c1), fmaxf(c2, c3)) + e.x;
            c0 = s0 + T01; c1 = s1 + T11; c2 = s2 + T21; c3 = s3 + T31;
            n1 = fmaxf(fmaxf(c0, c1), fmaxf(c2, c3)) + e.y;
            c0 = s0 + T02; c1 = s1 + T12; c2 = s2 + T22; c3 = s3 + T32;
            n2 = fmaxf(fmaxf(c0, c1), fmaxf(c2, c3)) + e.z;
            c0 = s0 + T03; c1 = s1 + T13; c2 = s2 + T23; c3 = s3 + T33;
            n3 = fmaxf(fmaxf(c0, c1), fmaxf(c2, c3)) + e.w;
            s0 = n0; s1 = n1; s2 = n2; s3 = n3;
            g_scores[t*BATCH + b] = make_float4(s0, s1, s2, s3);
        }

        float f0 = s0 + __ldg(endT+0);
        float f1 = s1 + __ldg(endT+1);
        float f2 = s2 + __ldg(endT+2);
        float f3 = s3 + __ldg(endT+3);
        int best = 0; float m = f0;              // strict >, first index wins
        if (f1 > m) { m = f1; best = 1; }
        if (f2 > m) { m = f2; best = 2; }
        if (f3 > m) { m = f3; best = 3; }
        s_best[b] = best;
    }
    __syncthreads();

    // ---------------- Phase B: per-step maps + composed chunk maps ----------
    {
        float tr[16];
        #pragma unroll
        for (int i = 0; i < 16; i++) tr[i] = __ldg(trans + i);

        #pragma unroll
        for (int it = 0; it < 4; it++) {
            int id = it*512 + tid;               // 0..2047
            int c = id >> 6, b = id & 63;
            int sbase = c * CL;
            int ns = (c == NCHUNK-1) ? (CL-1) : CL;

            unsigned m[CL];
            #pragma unroll
            for (int k = 0; k < CL; k++) {
                if (k < ns) {
                    float4 sc = g_scores[(sbase + k)*BATCH + b];
                    unsigned hh = 0;
                    #pragma unroll
                    for (int j = 0; j < 4; j++) {
                        float c0 = sc.x + tr[0*4+j];
                        float c1 = sc.y + tr[1*4+j];
                        float c2 = sc.z + tr[2*4+j];
                        float c3 = sc.w + tr[3*4+j];
                        int bp = 0; float mm = c0;
                        if (c1 > mm) { mm = c1; bp = 1; }
                        if (c2 > mm) { mm = c2; bp = 2; }
                        if (c3 > mm) { mm = c3; bp = 3; }
                        hh |= (unsigned)bp << (8*j);
                    }
                    m[k] = hh;
                    g_map32[(sbase + k)*BATCH + b] = hh;
                }
            }
            unsigned F = m[ns-1];
            #pragma unroll
            for (int k = CL-2; k >= 0; k--)
                if (k <= ns-2)
                    F = __byte_perm(m[k], 0, nibsel(F));
            s_cmap[c*BATCH + b] = F;
        }
    }
    __syncthreads();

    // ---------------- Phase C: suffix walk (threads 0..63) ------------------
    if (tid < 64) {
        int b = tid;
        int t = s_best[b];
        #pragma unroll
        for (int c = NCHUNK-1; c >= 0; c--) {
            s_btag[c*BATCH + b] = (uint8_t)t;    // tag at top boundary of chunk c
            t = __byte_perm(s_cmap[c*BATCH + b], 0, t) & 3;
        }
    }
    __syncthreads();

    // ---------------- Phase D: chunk replay -> packed tags in smem ----------
    #pragma unroll
    for (int it = 0; it < 4; it++) {
        int id = it*512 + tid;
        int c = id >> 6, b = id & 63;
        int sbase = c * CL;
        int ns = (c == NCHUNK-1) ? (CL-1) : CL;

        unsigned m[CL];
        #pragma unroll
        for (int k = 0; k < CL; k++)
            if (k < ns) m[k] = g_map32[(sbase + k)*BATCH + b];

        int tag = s_btag[c*BATCH + b];
        uint8_t tg[CL];
        if (c == NCHUNK-1) tg[CL-1] = (uint8_t)tag;   // t = 511 = best tag
        #pragma unroll
        for (int k = CL-1; k >= 0; k--) {
            if (k < ns) {
                tag = __byte_perm(m[k], 0, tag) & 3;
                tg[k] = (uint8_t)tag;
            }
        }
        uint4 packed;
        packed.x = tg[0]  | (tg[1]<<8)  | (tg[2]<<16)  | (tg[3]<<24);
        packed.y = tg[4]  | (tg[5]<<8)  | (tg[6]<<16)  | (tg[7]<<24);
        packed.z = tg[8]  | (tg[9]<<8)  | (tg[10]<<16) | (tg[11]<<24);
        packed.w = tg[12] | (tg[13]<<8) | (tg[14]<<16) | (tg[15]<<24);
        s_tag[c*BATCH + b] = packed;
    }
    __syncthreads();

    // ---------------- Phase E: coalesced float write-out --------------------
    // out4 idx: b = idx>>7, t4 = idx&127; tags at s_tag[(t4>>2)*64+b] word (t4&3)
    {
        float4* out4 = (float4*)out;
        #pragma unroll
        for (int it = 0; it < 16; it++) {
            int idx = it*512 + tid;              // 0..8191
            int b  = idx >> 7;
            int t4 = idx & 127;
            const unsigned* row = (const unsigned*)&s_tag[(t4 >> 2)*BATCH + b];
            unsigned w = row[t4 & 3];
            out4[idx] = make_float4((float)(w & 3), (float)((w >> 8) & 3),
                                    (float)((w >> 16) & 3), (float)((w >> 24) & 3));
        }
    }
}

// ---------------------------------------------------------------------------
// Bind inputs BY ELEMENT COUNT (robust to input-order permutation).
// The three 4-element vectors keep their relative order: b, start, end.
// __output__ dtype is float32 (established R7).
// ---------------------------------------------------------------------------
extern "C" void kernel_launch(void* const* d_in, const int* in_sizes, int n_in,
                              void* d_out, int out_size)
{
    const float* sent   = 0;
    const float* W      = 0;
    const float* bias   = 0;
    const float* startT = 0;
    const float* endT   = 0;
    const float* trans  = 0;

    int n4 = 0;
    for (int i = 0; i < n_in; i++) {
        int sz = in_sizes[i];
        const float* p = (const float*)d_in[i];
        if      (sz == BATCH*TT*HH) sent  = p;
        else if (sz == KK*HH)       W     = p;
        else if (sz == KK*KK)       trans = p;
        else if (sz == KK) {
            if      (n4 == 0) bias   = p;
            else if (n4 == 1) startT = p;
            else              endT   = p;
            n4++;
        }
    }
    float* out = (float*)d_out;                   // [64,512] float32

    k_emissions<<<ROWS/8, 256>>>(sent, W, bias);
    k_viterbi<<<1, 512>>>(startT, endT, trans, out);
}

// round 16
// speedup vs baseline: 1.4702x; 1.1700x over previous
#include <cuda_runtime.h>
#include <stdint.h>

#define BATCH 64
#define TT    512
#define HH    768
#define KK    4
#define ROWS  (BATCH*TT)   // 32768
#define NCHUNK 32
#define CL     16          // backtrack chunk length (NCHUNK*CL = 512)

typedef unsigned long long u64;

// Scratch (no cudaMalloc allowed). [t][b]-major for coalesced lane access.
__device__ float4   g_emis[(TT+8)*BATCH];   // [t*64+b], +8 rows pad for prefetch overrun
__device__ float4   g_scores[TT*BATCH];     // [t*64+b] viterbi scores
__device__ unsigned g_map32[TT*BATCH];      // [s*64+b] byte-form backpointer maps
__device__ unsigned g_cmap[NCHUNK*BATCH];   // [c*64+b] chunk-composed map
__device__ int      g_btag[NCHUNK*BATCH];   // [c*64+b] incoming tag for chunk replay
__device__ int      g_best[BATCH];

// pack byte-form map (bytes 0..3, values 0..3) into a PRMT nibble selector
__device__ __forceinline__ unsigned nibsel(unsigned x) {
    unsigned y = x | (x >> 4);
    unsigned t = y & 0x00FF00FFu;
    return (t | (t >> 8)) & 0xFFFFu;
}

// ---- Blackwell packed f32x2 helpers (exact elementwise IEEE fp32) ----------
__device__ __forceinline__ u64 f2pack(float lo, float hi) {
    u64 r; asm("mov.b64 %0, {%1, %2};" : "=l"(r) : "f"(lo), "f"(hi)); return r;
}
__device__ __forceinline__ void f2unpack(float& lo, float& hi, u64 v) {
    asm("mov.b64 {%0, %1}, %2;" : "=f"(lo), "=f"(hi) : "l"(v));
}
__device__ __forceinline__ u64 f2add(u64 a, u64 b) {
    u64 r; asm("add.rn.f32x2 %0, %1, %2;" : "=l"(r) : "l"(a), "l"(b)); return r;
}

// ---------------------------------------------------------------------------
// K1: emissions[b,t,k] = sum_h sentences[b,t,h]*W[k,h] + bias[k]
// warp-per-row, W in shared, float4 coalesced, shuffle reduce. HBM-bound.
// Stores TRANSPOSED: g_emis[t*64 + b].  (unchanged from R8)
// ---------------------------------------------------------------------------
__global__ __launch_bounds__(256) void k_emissions(
    const float* __restrict__ sent,   // [B,T,H]
    const float* __restrict__ W,      // [K,H]
    const float* __restrict__ bias)   // [K]
{
    __shared__ float4 sW[KK][HH/4];   // 12 KB
    __shared__ float  sb[KK];
    int tid = threadIdx.x;

    const float4* W4 = (const float4*)W;
    for (int i = tid; i < KK*(HH/4); i += blockDim.x)
        sW[i/(HH/4)][i%(HH/4)] = W4[i];
    if (tid < KK) sb[tid] = bias[tid];
    __syncthreads();

    int warp = tid >> 5, lane = tid & 31;
    int row  = blockIdx.x * (blockDim.x >> 5) + warp;
    if (row >= ROWS) return;

    const float4* x = (const float4*)(sent + (size_t)row * HH);
    float a0 = 0.f, a1 = 0.f, a2 = 0.f, a3 = 0.f;
    #pragma unroll
    for (int i = 0; i < HH/128; i++) {            // 6 iterations
        int idx = i*32 + lane;
        float4 v  = x[idx];
        float4 w0 = sW[0][idx];
        float4 w1 = sW[1][idx];
        float4 w2 = sW[2][idx];
        float4 w3 = sW[3][idx];
        a0 += v.x*w0.x + v.y*w0.y + v.z*w0.z + v.w*w0.w;
        a1 += v.x*w1.x + v.y*w1.y + v.z*w1.z + v.w*w1.w;
        a2 += v.x*w2.x + v.y*w2.y + v.z*w2.z + v.w*w2.w;
        a3 += v.x*w3.x + v.y*w3.y + v.z*w3.z + v.w*w3.w;
    }
    #pragma unroll
    for (int d = 16; d; d >>= 1) {
        a0 += __shfl_xor_sync(0xffffffffu, a0, d);
        a1 += __shfl_xor_sync(0xffffffffu, a1, d);
        a2 += __shfl_xor_sync(0xffffffffu, a2, d);
        a3 += __shfl_xor_sync(0xffffffffu, a3, d);
    }
    if (lane == 0) {
        int b = row >> 9;
        int t = row & (TT-1);
        g_emis[t*BATCH + b] = make_float4(a0 + sb[0], a1 + sb[1], a2 + sb[2], a3 + sb[3]);
    }
}

// ---------------------------------------------------------------------------
// K2: Viterbi forward scan with PACKED f32x2 adds. thread = batch,
// 2 blocks x 32 (each warp on its own SM -> private L1tex path).
// Scores kept as two packed f32x2 pairs; stored via one STG.128.
// EXACT: packed add = elementwise IEEE add; fp max exactly associative.
// ---------------------------------------------------------------------------
__global__ __launch_bounds__(32) void k_forward(
    const float* __restrict__ startT,
    const float* __restrict__ endT,
    const float* __restrict__ trans)   // [K,K], trans[i*4+j]
{
    int b = blockIdx.x * 32 + threadIdx.x;   // 0..63

    // packed transition columns: C01[j]=(T[0][j],T[1][j]), C23[j]=(T[2][j],T[3][j])
    u64 C01[4], C23[4];
    #pragma unroll
    for (int j = 0; j < 4; j++) {
        C01[j] = f2pack(__ldg(trans + 0*4 + j), __ldg(trans + 1*4 + j));
        C23[j] = f2pack(__ldg(trans + 2*4 + j), __ldg(trans + 3*4 + j));
    }

    float4 e0 = g_emis[0*BATCH + b];
    float s0 = __ldg(startT+0) + e0.x;
    float s1 = __ldg(startT+1) + e0.y;
    float s2 = __ldg(startT+2) + e0.z;
    float s3 = __ldg(startT+3) + e0.w;
    g_scores[0*BATCH + b] = make_float4(s0, s1, s2, s3);

    u64 P01 = f2pack(s0, s1);
    u64 P23 = f2pack(s2, s3);

    float4 buf[8];
    #pragma unroll
    for (int j = 0; j < 8; j++) buf[j] = g_emis[(1 + j)*BATCH + b];

    // main: t = 1..504, unconditional prefetch (array padded to TT+8 rows)
    for (int base = 1; base <= 497; base += 8) {
        #pragma unroll
        for (int j = 0; j < 8; j++) {
            int t = base + j;
            float4 e = buf[j];
            buf[j] = g_emis[(t + 8)*BATCH + b];

            float m0, m1, m2, m3;
            {
                u64 a = f2add(P01, C01[0]); u64 c = f2add(P23, C23[0]);
                float x0,x1,y0,y1; f2unpack(x0,x1,a); f2unpack(y0,y1,c);
                m0 = fmaxf(fmaxf(x0,x1), fmaxf(y0,y1));
            }
            {
                u64 a = f2add(P01, C01[1]); u64 c = f2add(P23, C23[1]);
                float x0,x1,y0,y1; f2unpack(x0,x1,a); f2unpack(y0,y1,c);
                m1 = fmaxf(fmaxf(x0,x1), fmaxf(y0,y1));
            }
            {
                u64 a = f2add(P01, C01[2]); u64 c = f2add(P23, C23[2]);
                float x0,x1,y0,y1; f2unpack(x0,x1,a); f2unpack(y0,y1,c);
                m2 = fmaxf(fmaxf(x0,x1), fmaxf(y0,y1));
            }
            {
                u64 a = f2add(P01, C01[3]); u64 c = f2add(P23, C23[3]);
                float x0,x1,y0,y1; f2unpack(x0,x1,a); f2unpack(y0,y1,c);
                m3 = fmaxf(fmaxf(x0,x1), fmaxf(y0,y1));
            }
            P01 = f2add(f2pack(m0, m1), f2pack(e.x, e.y));
            P23 = f2add(f2pack(m2, m3), f2pack(e.z, e.w));

            ulonglong2 st; st.x = P01; st.y = P23;
            *(ulonglong2*)&g_scores[t*BATCH + b] = st;
        }
    }

    // tail: t = 505..511 (buf[j] holds em[505+j] after last group)
    #pragma unroll
    for (int j = 0; j < 7; j++) {
        int t = 505 + j;
        float4 e = buf[j];
        float m0, m1, m2, m3;
        {
            u64 a = f2add(P01, C01[0]); u64 c = f2add(P23, C23[0]);
            float x0,x1,y0,y1; f2unpack(x0,x1,a); f2unpack(y0,y1,c);
            m0 = fmaxf(fmaxf(x0,x1), fmaxf(y0,y1));
        }
        {
            u64 a = f2add(P01, C01[1]); u64 c = f2add(P23, C23[1]);
            float x0,x1,y0,y1; f2unpack(x0,x1,a); f2unpack(y0,y1,c);
            m1 = fmaxf(fmaxf(x0,x1), fmaxf(y0,y1));
        }
        {
            u64 a = f2add(P01, C01[2]); u64 c = f2add(P23, C23[2]);
            float x0,x1,y0,y1; f2unpack(x0,x1,a); f2unpack(y0,y1,c);
            m2 = fmaxf(fmaxf(x0,x1), fmaxf(y0,y1));
        }
        {
            u64 a = f2add(P01, C01[3]); u64 c = f2add(P23, C23[3]);
            float x0,x1,y0,y1; f2unpack(x0,x1,a); f2unpack(y0,y1,c);
            m3 = fmaxf(fmaxf(x0,x1), fmaxf(y0,y1));
        }
        P01 = f2add(f2pack(m0, m1), f2pack(e.x, e.y));
        P23 = f2add(f2pack(m2, m3), f2pack(e.z, e.w));

        ulonglong2 st; st.x = P01; st.y = P23;
        *(ulonglong2*)&g_scores[t*BATCH + b] = st;
    }

    // final: add end transitions, argmax over 4 (strict >, first index wins)
    float s0f, s1f, s2f, s3f;
    f2unpack(s0f, s1f, P01);
    f2unpack(s2f, s3f, P23);
    float f0 = s0f + __ldg(endT+0);
    float f1 = s1f + __ldg(endT+1);
    float f2 = s2f + __ldg(endT+2);
    float f3 = s3f + __ldg(endT+3);
    int best = 0; float m = f0;
    if (f1 > m) { m = f1; best = 1; }
    if (f2 > m) { m = f2; best = 2; }
    if (f3 > m) { m = f3; best = 3; }
    g_best[b] = best;
}

// ---------------------------------------------------------------------------
// K3: per (chunk c, batch b): per-step backpointer maps
//   f_s[j] = argmax_i ( scores[s][i] + trans[i][j] ), first-index wins,
// stored + chunk-composed map F_c (exact integer composition via PRMT).
// (unchanged from R8)
// ---------------------------------------------------------------------------
__global__ __launch_bounds__(64) void k_chunk(const float* __restrict__ trans)
{
    int b = threadIdx.x;
    int c = blockIdx.x;
    int sbase = c * CL;
    int ns = (c == NCHUNK-1) ? (CL-1) : CL;   // chunk 31 covers s=496..510

    float tr[16];
    #pragma unroll
    for (int i = 0; i < 16; i++) tr[i] = __ldg(trans + i);

    unsigned m[CL];
    #pragma unroll
    for (int k = 0; k < CL; k++) {
        if (k < ns) {
            float4 sc = g_scores[(sbase + k)*BATCH + b];
            unsigned hh = 0;
            #pragma unroll
            for (int j = 0; j < 4; j++) {
                float c0 = sc.x + tr[0*4+j];
                float c1 = sc.y + tr[1*4+j];
                float c2 = sc.z + tr[2*4+j];
                float c3 = sc.w + tr[3*4+j];
                int bp = 0; float mm = c0;
                if (c1 > mm) { mm = c1; bp = 1; }
                if (c2 > mm) { mm = c2; bp = 2; }
                if (c3 > mm) { mm = c3; bp = 3; }
                hh |= (unsigned)bp << (8*j);
            }
            m[k] = hh;
            g_map32[(sbase + k)*BATCH + b] = hh;
        }
    }

    unsigned F = m[ns-1];
    #pragma unroll
    for (int k = CL-2; k >= 0; k--)
        if (k <= ns-2)
            F = __byte_perm(m[k], 0, nibsel(F));
    g_cmap[c*BATCH + b] = F;
}

// ---------------------------------------------------------------------------
// K3b: suffix walk over chunk maps -> incoming tag per chunk; writes out[511].
// (unchanged from R8)
// ---------------------------------------------------------------------------
__global__ __launch_bounds__(64) void k_btag(float* __restrict__ out)
{
    int b = threadIdx.x;
    unsigned Fs[NCHUNK];
    #pragma unroll
    for (int c = 0; c < NCHUNK; c++) Fs[c] = g_cmap[c*BATCH + b];

    int t = g_best[b];
    out[b*TT + (TT-1)] = (float)t;
    #pragma unroll
    for (int c = NCHUNK-1; c >= 0; c--) {
        g_btag[c*BATCH + b] = t;
        t = __byte_perm(Fs[c], 0, t) & 3;
    }
}

// ---------------------------------------------------------------------------
// K4: parallel chunk replay. thread (c,b): 16 PRMT steps, coalesced map loads.
// (unchanged from R8)
// ---------------------------------------------------------------------------
__global__ __launch_bounds__(64) void k_replay(float* __restrict__ out)
{
    int b = threadIdx.x;
    int c = blockIdx.x;
    int sbase = c * CL;
    int ns = (c == NCHUNK-1) ? (CL-1) : CL;

    unsigned m[CL];
    #pragma unroll
    for (int k = 0; k < CL; k++)
        if (k < ns) m[k] = g_map32[(sbase + k)*BATCH + b];

    int tag = g_btag[c*BATCH + b];
    #pragma unroll
    for (int k = CL-1; k >= 0; k--) {
        if (k < ns) {
            tag = __byte_perm(m[k], 0, tag) & 3;
            out[b*TT + sbase + k] = (float)tag;
        }
    }
}

// ---------------------------------------------------------------------------
// Bind inputs BY ELEMENT COUNT (robust to input-order permutation).
// The three 4-element vectors keep their relative order: b, start, end.
// __output__ dtype is float32 (established R7).
// ---------------------------------------------------------------------------
extern "C" void kernel_launch(void* const* d_in, const int* in_sizes, int n_in,
                              void* d_out, int out_size)
{
    const float* sent   = 0;
    const float* W      = 0;
    const float* bias   = 0;
    const float* startT = 0;
    const float* endT   = 0;
    const float* trans  = 0;

    int n4 = 0;
    for (int i = 0; i < n_in; i++) {
        int sz = in_sizes[i];
        const float* p = (const float*)d_in[i];
        if      (sz == BATCH*TT*HH) sent  = p;
        else if (sz == KK*HH)       W     = p;
        else if (sz == KK*KK)       trans = p;
        else if (sz == KK) {
            if      (n4 == 0) bias   = p;
            else if (n4 == 1) startT = p;
            else              endT   = p;
            n4++;
        }
    }
    float* out = (float*)d_out;                   // [64,512] float32

    k_emissions<<<ROWS/8, 256>>>(sent, W, bias);
    k_forward<<<2, 32>>>(startT, endT, trans);
    k_chunk<<<NCHUNK, 64>>>(trans);
    k_btag<<<1, 64>>>(out);
    k_replay<<<NCHUNK, 64>>>(out);
}